// round 1
// baseline (speedup 1.0000x reference)
#include <cuda_runtime.h>
#include <cuda_bf16.h>
#include <math.h>

// Problem constants
#define B_    4
#define T_    4
#define HH_   28
#define WW_   28
#define E_    512
#define NH_   8
#define HC_   64
#define HWP_  784            // 28*28
#define NN_   3136           // T*HW
#define ROWS_ 12544          // B*N
#define SCALE_ 0.125f        // hc^-0.5

// Scratch buffers (static device memory — no allocation in kernel_launch)
__device__ float g_qkv[ROWS_ * 3 * E_];   // [B*N, 1536]  (3, nh, hc) packed
__device__ float g_sp [ROWS_ * E_];       // spatial attention output [B*N, C]
__device__ float g_qt [ROWS_ * E_];       // temporal queries (scaled) [B*N, C]
__device__ float g_ot [ROWS_ * E_];       // o_th + o_tw [B*N, C]

// ---------------------------------------------------------------------------
// Tiled fp32 GEMM: C[M,N] = A[M,K] @ W[N,K]^T (+bias), with epilogue modes:
//   mode 0: C = acc + bias
//   mode 1: C = (acc + bias) * scl
//   mode 2: C = C + alpha[n] * (acc + bias)      (C preloaded with xs)
// BM=BN=128, BK=16, 256 threads, 8x8 microtile. All dims divide exactly.
// ---------------------------------------------------------------------------
__global__ __launch_bounds__(256)
void gemm_kernel(const float* __restrict__ A, const float* __restrict__ W,
                 const float* __restrict__ bias, float* __restrict__ C,
                 const float* __restrict__ alpha,
                 int M, int N, int K, int mode, float scl)
{
    __shared__ float As[16][128];
    __shared__ float Bs[16][128];
    const int bm = blockIdx.y * 128;
    const int bn = blockIdx.x * 128;
    const int tid = threadIdx.x;
    const int tx = tid & 15;        // 0..15 -> n
    const int ty = tid >> 4;        // 0..15 -> m
    float acc[8][8];
#pragma unroll
    for (int i = 0; i < 8; i++)
#pragma unroll
        for (int j = 0; j < 8; j++) acc[i][j] = 0.f;

    for (int k0 = 0; k0 < K; k0 += 16) {
#pragma unroll
        for (int it = 0; it < 2; it++) {
            int r  = (tid >> 2) + it * 64;   // 0..127
            int c4 = (tid & 3) * 4;          // 0,4,8,12
            float4 a = *(const float4*)(A + (size_t)(bm + r) * K + k0 + c4);
            As[c4 + 0][r] = a.x; As[c4 + 1][r] = a.y;
            As[c4 + 2][r] = a.z; As[c4 + 3][r] = a.w;
            float4 b = *(const float4*)(W + (size_t)(bn + r) * K + k0 + c4);
            Bs[c4 + 0][r] = b.x; Bs[c4 + 1][r] = b.y;
            Bs[c4 + 2][r] = b.z; Bs[c4 + 3][r] = b.w;
        }
        __syncthreads();
#pragma unroll
        for (int k = 0; k < 16; k++) {
            float4 a0 = *(const float4*)&As[k][ty * 8];
            float4 a1 = *(const float4*)&As[k][ty * 8 + 4];
            float4 b0 = *(const float4*)&Bs[k][tx * 8];
            float4 b1 = *(const float4*)&Bs[k][tx * 8 + 4];
            float av[8] = {a0.x, a0.y, a0.z, a0.w, a1.x, a1.y, a1.z, a1.w};
            float bv[8] = {b0.x, b0.y, b0.z, b0.w, b1.x, b1.y, b1.z, b1.w};
#pragma unroll
            for (int i = 0; i < 8; i++)
#pragma unroll
                for (int j = 0; j < 8; j++) acc[i][j] += av[i] * bv[j];
        }
        __syncthreads();
    }

#pragma unroll
    for (int i = 0; i < 8; i++) {
        int mrow = bm + ty * 8 + i;
#pragma unroll
        for (int j = 0; j < 8; j++) {
            int ncol = bn + tx * 8 + j;
            float v = acc[i][j] + bias[ncol];
            if (mode == 1) v *= scl;
            size_t idx = (size_t)mrow * N + ncol;
            if (mode == 2) v = C[idx] + alpha[ncol] * v;
            C[idx] = v;
        }
    }
}

// ---------------------------------------------------------------------------
// Spatial attention: 128 independent problems (bt in 0..15, head in 0..7),
// Lq=Lk=784, d=64. Warp-per-query-row online softmax, key tiles of 32.
// q,k,v read directly from g_qkv layout [B*N, (3, nh, hc)].
// Output into g_sp [B*N, C] (head-interleaved).
// ---------------------------------------------------------------------------
__global__ __launch_bounds__(256)
void spatial_attn_kernel(const float* __restrict__ qkv, float* __restrict__ out)
{
    const int bt   = blockIdx.z;          // 0..15  (b*T + t)
    const int head = blockIdx.y;          // 0..7
    const int q0   = blockIdx.x * 8;      // query rows per block
    const int warp = threadIdx.x >> 5;
    const int lane = threadIdx.x & 31;
    const int qrow = q0 + warp;           // < 784 always (784/8 = 98 blocks)

    __shared__ float k_s[64 * 33];        // transposed [c][j], pitch 33
    __shared__ float v_s[32 * 64];        // [j][c]
    __shared__ float q_s[8 * 64];

    // cooperative q staging
    for (int i = threadIdx.x; i < 8 * 64; i += 256) {
        int rw = q0 + (i >> 6), c = i & 63;
        q_s[i] = qkv[(size_t)(bt * HWP_ + rw) * 1536 + head * 64 + c];
    }
    __syncthreads();

    float q[64];
#pragma unroll
    for (int c = 0; c < 64; c++) q[c] = q_s[warp * 64 + c] * SCALE_;

    float m = -1e30f, l = 0.f, o0 = 0.f, o1 = 0.f;

    for (int kt = 0; kt < HWP_; kt += 32) {
        __syncthreads();
        for (int i = threadIdx.x; i < 32 * 64; i += 256) {
            int c = i & 63, j = i >> 6;
            int kk = kt + j;
            float kK = 0.f, kV = 0.f;
            if (kk < HWP_) {
                size_t base = (size_t)(bt * HWP_ + kk) * 1536 + head * 64 + c;
                kK = qkv[base + 512];
                kV = qkv[base + 1024];
            }
            k_s[c * 33 + j] = kK;
            v_s[j * 64 + c] = kV;
        }
        __syncthreads();

        float s = 0.f;
#pragma unroll
        for (int c = 0; c < 64; c++) s += q[c] * k_s[c * 33 + lane];
        bool valid = (kt + lane) < HWP_;
        s = valid ? s : -1e30f;

        float smax = s;
#pragma unroll
        for (int off = 16; off; off >>= 1)
            smax = fmaxf(smax, __shfl_xor_sync(0xffffffffu, smax, off));
        float mnew = fmaxf(m, smax);
        float p = __expf(s - mnew);
        float corr = __expf(m - mnew);
        float psum = p;
#pragma unroll
        for (int off = 16; off; off >>= 1)
            psum += __shfl_xor_sync(0xffffffffu, psum, off);
        l = l * corr + psum;
        o0 *= corr; o1 *= corr;
        m = mnew;
#pragma unroll
        for (int j = 0; j < 32; j++) {
            float pj = __shfl_sync(0xffffffffu, p, j);
            o0 += pj * v_s[j * 64 + lane];
            o1 += pj * v_s[j * 64 + lane + 32];
        }
    }
    float inv = 1.f / l;
    size_t ob = (size_t)(bt * HWP_ + qrow) * E_ + head * 64;
    out[ob + lane]      = o0 * inv;
    out[ob + lane + 32] = o1 * inv;
}

// ---------------------------------------------------------------------------
// Axial temporal attention (th: fs=1, vs=28 ; tw: fs=28, vs=1).
// Problems: (b, fixed) x head, rows r = t*28 + var (L=112). Block-causal mask
// == restrict keys to prefix (t_q+1)*28 (exp(-1000) contributions are 0).
// q from g_qt (already scaled), k/v from g_qkv cache. accum: = vs +=.
// ---------------------------------------------------------------------------
__global__ __launch_bounds__(256)
void temporal_attn_kernel(const float* __restrict__ qkv, const float* __restrict__ qt,
                          float* __restrict__ ot, int fs, int vs, int accum)
{
    const int bz    = blockIdx.z;             // 0..111 : b*28 + fixed
    const int b     = bz / 28;
    const int fixed = bz % 28;
    const int head  = blockIdx.y;
    const int r0    = blockIdx.x * 8;
    const int warp  = threadIdx.x >> 5;
    const int lane  = threadIdx.x & 31;
    const int r     = r0 + warp;              // < 112
    const int tq    = r / 28;
    const int varq  = r % 28;
    const int nq    = tq * HWP_ + fixed * fs + varq * vs;
    const int rowq  = b * NN_ + nq;

    __shared__ float k_s[64 * 33];
    __shared__ float v_s[32 * 64];
    __shared__ float q_s[8 * 64];

    for (int i = threadIdx.x; i < 8 * 64; i += 256) {
        int rw = r0 + (i >> 6), c = i & 63;
        int nqq = (rw / 28) * HWP_ + fixed * fs + (rw % 28) * vs;
        q_s[i] = qt[(size_t)(b * NN_ + nqq) * E_ + head * 64 + c];
    }
    __syncthreads();

    float q[64];
#pragma unroll
    for (int c = 0; c < 64; c++) q[c] = q_s[warp * 64 + c];

    const int kmax  = (tq + 1) * 28;                 // per-warp causal prefix
    const int kmaxb = ((r0 + 7) / 28 + 1) * 28;      // block max (<=112)

    float m = -1e30f, l = 0.f, o0 = 0.f, o1 = 0.f;

    for (int kt = 0; kt < kmaxb; kt += 32) {
        __syncthreads();
        for (int i = threadIdx.x; i < 32 * 64; i += 256) {
            int c = i & 63, j = i >> 6;
            int kk = kt + j;
            float kK = 0.f, kV = 0.f;
            if (kk < kmaxb) {
                int nk = (kk / 28) * HWP_ + fixed * fs + (kk % 28) * vs;
                size_t base = (size_t)(b * NN_ + nk) * 1536 + head * 64 + c;
                kK = qkv[base + 512];
                kV = qkv[base + 1024];
            }
            k_s[c * 33 + j] = kK;
            v_s[j * 64 + c] = kV;
        }
        __syncthreads();

        float s = 0.f;
#pragma unroll
        for (int c = 0; c < 64; c++) s += q[c] * k_s[c * 33 + lane];
        bool valid = (kt + lane) < kmax;
        s = valid ? s : -1e30f;

        float smax = s;
#pragma unroll
        for (int off = 16; off; off >>= 1)
            smax = fmaxf(smax, __shfl_xor_sync(0xffffffffu, smax, off));
        float mnew = fmaxf(m, smax);
        float p = __expf(s - mnew);
        float corr = __expf(m - mnew);
        float psum = p;
#pragma unroll
        for (int off = 16; off; off >>= 1)
            psum += __shfl_xor_sync(0xffffffffu, psum, off);
        l = l * corr + psum;
        o0 *= corr; o1 *= corr;
        m = mnew;
#pragma unroll
        for (int j = 0; j < 32; j++) {
            float pj = __shfl_sync(0xffffffffu, p, j);
            o0 += pj * v_s[j * 64 + lane];
            o1 += pj * v_s[j * 64 + lane + 32];
        }
    }
    float inv = 1.f / l;
    size_t ob = (size_t)rowq * E_ + head * 64;
    if (accum) {
        ot[ob + lane]      += o0 * inv;
        ot[ob + lane + 32] += o1 * inv;
    } else {
        ot[ob + lane]      = o0 * inv;
        ot[ob + lane + 32] = o1 * inv;
    }
}

// ---------------------------------------------------------------------------
extern "C" void kernel_launch(void* const* d_in, const int* in_sizes, int n_in,
                              void* d_out, int out_size)
{
    const float* x      = (const float*)d_in[0];   // [B,N,E]
    const float* w_in   = (const float*)d_in[1];   // [3E,E]
    const float* b_in   = (const float*)d_in[2];   // [3E]
    const float* w_out  = (const float*)d_in[3];   // [E,E]
    const float* b_out  = (const float*)d_in[4];   // [E]
    const float* w_t    = (const float*)d_in[5];   // [E,E]
    const float* b_t    = (const float*)d_in[6];   // [E]
    const float* w_to   = (const float*)d_in[7];   // [E,E]
    const float* b_to   = (const float*)d_in[8];   // [E]
    const float* alpha  = (const float*)d_in[9];   // [E]
    float* out = (float*)d_out;                    // [B,N,E]

    float *qkv, *sp, *qt, *ot;
    cudaGetSymbolAddress((void**)&qkv, g_qkv);
    cudaGetSymbolAddress((void**)&sp,  g_sp);
    cudaGetSymbolAddress((void**)&qt,  g_qt);
    cudaGetSymbolAddress((void**)&ot,  g_ot);

    dim3 blk(256);

    // 1) qkv projection: [12544,1536] = x @ w_in^T + b_in
    gemm_kernel<<<dim3(1536 / 128, ROWS_ / 128), blk>>>(
        x, w_in, b_in, qkv, nullptr, ROWS_, 1536, E_, 0, 1.f);

    // 2) spatial attention
    spatial_attn_kernel<<<dim3(HWP_ / 8, NH_, B_ * T_), blk>>>(qkv, sp);

    // 3) xs = sp @ w_out^T + b_out  -> d_out
    gemm_kernel<<<dim3(E_ / 128, ROWS_ / 128), blk>>>(
        sp, w_out, b_out, out, nullptr, ROWS_, E_, E_, 0, 1.f);

    // 4) q_t = (x @ w_t^T + b_t) * scale
    gemm_kernel<<<dim3(E_ / 128, ROWS_ / 128), blk>>>(
        x, w_t, b_t, qt, nullptr, ROWS_, E_, E_, 1, SCALE_);

    // 5) temporal-H attention (fixed = w): ot = o_th
    temporal_attn_kernel<<<dim3(112 / 8, NH_, B_ * WW_), blk>>>(
        qkv, qt, ot, /*fs=*/1, /*vs=*/28, /*accum=*/0);

    // 6) temporal-W attention (fixed = y): ot += o_tw
    temporal_attn_kernel<<<dim3(112 / 8, NH_, B_ * HH_), blk>>>(
        qkv, qt, ot, /*fs=*/28, /*vs=*/1, /*accum=*/1);

    // 7) out = xs + alpha * (ot @ w_to^T + b_to)
    gemm_kernel<<<dim3(E_ / 128, ROWS_ / 128), blk>>>(
        ot, w_to, b_to, out, alpha, ROWS_, E_, E_, 2, 1.f);
}

// round 2
// speedup vs baseline: 2.5081x; 2.5081x over previous
#include <cuda_runtime.h>
#include <cuda_bf16.h>
#include <math.h>

// Problem constants
#define B_    4
#define T_    4
#define HH_   28
#define WW_   28
#define E_    512
#define NH_   8
#define HC_   64
#define HWP_  784            // 28*28
#define NN_   3136           // T*HW
#define ROWS_ 12544          // B*N
#define SCALE_ 0.125f        // hc^-0.5

// Scratch buffers (static device memory — no allocation in kernel_launch)
__device__ float g_qkv[ROWS_ * 3 * E_];   // [B*N, 1536]
__device__ float g_sp [ROWS_ * E_];       // spatial attention output
__device__ float g_qt [ROWS_ * E_];       // temporal queries (scaled)
__device__ float g_ot [ROWS_ * E_];       // o_th + o_tw

// ---------------------------------------------------------------------------
// Tiled fp32 GEMM: C[M,N] = A[M,K] @ W[N,K]^T (+bias). Epilogue modes:
//   0: C = acc + bias   1: C = (acc+bias)*scl   2: C = C + alpha[n]*(acc+bias)
// ---------------------------------------------------------------------------
__global__ __launch_bounds__(256)
void gemm_kernel(const float* __restrict__ A, const float* __restrict__ W,
                 const float* __restrict__ bias, float* __restrict__ C,
                 const float* __restrict__ alpha,
                 int M, int N, int K, int mode, float scl)
{
    __shared__ float As[16][128];
    __shared__ float Bs[16][128];
    const int bm = blockIdx.y * 128;
    const int bn = blockIdx.x * 128;
    const int tid = threadIdx.x;
    const int tx = tid & 15;
    const int ty = tid >> 4;
    float acc[8][8];
#pragma unroll
    for (int i = 0; i < 8; i++)
#pragma unroll
        for (int j = 0; j < 8; j++) acc[i][j] = 0.f;

    for (int k0 = 0; k0 < K; k0 += 16) {
#pragma unroll
        for (int it = 0; it < 2; it++) {
            int r  = (tid >> 2) + it * 64;
            int c4 = (tid & 3) * 4;
            float4 a = *(const float4*)(A + (size_t)(bm + r) * K + k0 + c4);
            As[c4 + 0][r] = a.x; As[c4 + 1][r] = a.y;
            As[c4 + 2][r] = a.z; As[c4 + 3][r] = a.w;
            float4 b = *(const float4*)(W + (size_t)(bn + r) * K + k0 + c4);
            Bs[c4 + 0][r] = b.x; Bs[c4 + 1][r] = b.y;
            Bs[c4 + 2][r] = b.z; Bs[c4 + 3][r] = b.w;
        }
        __syncthreads();
#pragma unroll
        for (int k = 0; k < 16; k++) {
            float4 a0 = *(const float4*)&As[k][ty * 8];
            float4 a1 = *(const float4*)&As[k][ty * 8 + 4];
            float4 b0 = *(const float4*)&Bs[k][tx * 8];
            float4 b1 = *(const float4*)&Bs[k][tx * 8 + 4];
            float av[8] = {a0.x, a0.y, a0.z, a0.w, a1.x, a1.y, a1.z, a1.w};
            float bv[8] = {b0.x, b0.y, b0.z, b0.w, b1.x, b1.y, b1.z, b1.w};
#pragma unroll
            for (int i = 0; i < 8; i++)
#pragma unroll
                for (int j = 0; j < 8; j++) acc[i][j] += av[i] * bv[j];
        }
        __syncthreads();
    }

#pragma unroll
    for (int i = 0; i < 8; i++) {
        int mrow = bm + ty * 8 + i;
#pragma unroll
        for (int j = 0; j < 8; j++) {
            int ncol = bn + tx * 8 + j;
            float v = acc[i][j] + bias[ncol];
            if (mode == 1) v *= scl;
            size_t idx = (size_t)mrow * N + ncol;
            if (mode == 2) v = C[idx] + alpha[ncol] * v;
            C[idx] = v;
        }
    }
}

// ---------------------------------------------------------------------------
// Flash attention, block-tiled. BQ=BK=64, D=64, 256 threads (16x16), each
// thread owns a 4x4 microtile of S/P (keys strided 16) and of O (dims x4).
// TMP=0: spatial (bt = blockIdx.z, Lq=Lk=784, no mask, q from qkv * SCALE_)
// TMP=1: temporal axial (z = b*28+fixed, L=112, frame-causal prefix mask,
//        q from g_qt pre-scaled, k index = (kk/28)*784 + fixed*fs + (kk%28)*vs)
// Dynamic smem: Qs[64][64] | KPs[64][68] (K tile, then P tile) | Vs[64][64]
// ---------------------------------------------------------------------------
#define FSMEM ((4096 + 64*68 + 4096) * 4)

template<int TMP>
__global__ __launch_bounds__(256)
void flash_attn(const float* __restrict__ qkv, const float* __restrict__ qsrc,
                float* __restrict__ out, int fs, int vs, int accum)
{
    extern __shared__ float sm[];
    float* Qs  = sm;                  // [r][d] pitch 64
    float* KPs = sm + 4096;           // K: [j][d] pitch 68 ; P: [r][k] pitch 68
    float* Vs  = sm + 4096 + 64*68;   // [k][d] pitch 64

    const int tid  = threadIdx.x;
    const int tx   = tid & 15;
    const int ty   = tid >> 4;
    const int head = blockIdx.y;
    const int q0   = blockIdx.x * 64;

    int b = 0, fixed = 0, bt = 0;
    if (TMP) { b = blockIdx.z / 28; fixed = blockIdx.z % 28; }
    else     { bt = blockIdx.z; }

    const int Lq = TMP ? 112 : HWP_;
    const int lastr = min(q0 + 63, Lq - 1);
    const int kmaxb = TMP ? (lastr / 28 + 1) * 28 : HWP_;

    // ---- stage Q tile (once) ----
    for (int f = tid; f < 1024; f += 256) {
        int r = f >> 4, c4 = (f & 15) << 2;
        int rq = min(q0 + r, Lq - 1);
        if (TMP) {
            int nq = (rq / 28) * HWP_ + fixed * fs + (rq % 28) * vs;
            *(float4*)(Qs + r * 64 + c4) =
                *(const float4*)(qsrc + (size_t)(b * NN_ + nq) * E_ + head * HC_ + c4);
        } else {
            float4 v = *(const float4*)(qsrc + (size_t)(bt * HWP_ + rq) * 1536 + head * HC_ + c4);
            v.x *= SCALE_; v.y *= SCALE_; v.z *= SCALE_; v.w *= SCALE_;
            *(float4*)(Qs + r * 64 + c4) = v;
        }
    }

    float m[4], l[4], o[4][4];
    int rowkmax[4];
#pragma unroll
    for (int i = 0; i < 4; i++) {
        m[i] = -1e30f; l[i] = 0.f;
#pragma unroll
        for (int j = 0; j < 4; j++) o[i][j] = 0.f;
        int r = q0 + ty * 4 + i;
        rowkmax[i] = TMP ? min((r / 28 + 1) * 28, 112) : HWP_;
    }

    for (int kt = 0; kt < kmaxb; kt += 64) {
        __syncthreads();   // prev PV reads of KPs/Vs done; also orders Q staging
        // ---- stage K (natural, pitch 68) and V (natural, pitch 64) ----
        for (int f = tid; f < 1024; f += 256) {
            int j = f >> 4, c4 = (f & 15) << 2;
            int kk = min(kt + j, kmaxb - 1);
            size_t base;
            if (TMP) {
                int nk = (kk / 28) * HWP_ + fixed * fs + (kk % 28) * vs;
                base = (size_t)(b * NN_ + nk) * 1536 + head * HC_ + c4;
            } else {
                base = (size_t)(bt * HWP_ + kk) * 1536 + head * HC_ + c4;
            }
            *(float4*)(KPs + j * 68 + c4) = *(const float4*)(qkv + base + 512);
            *(float4*)(Vs  + j * 64 + c4) = *(const float4*)(qkv + base + 1024);
        }
        __syncthreads();

        // ---- S = Q @ K^T : rows ty*4+i, cols tx+16*jj ----
        float s[4][4];
#pragma unroll
        for (int i = 0; i < 4; i++)
#pragma unroll
            for (int j = 0; j < 4; j++) s[i][j] = 0.f;

#pragma unroll
        for (int d = 0; d < 64; d += 4) {
            float4 a[4], bv[4];
#pragma unroll
            for (int i = 0; i < 4; i++)
                a[i] = *(const float4*)(Qs + (ty * 4 + i) * 64 + d);
#pragma unroll
            for (int jj = 0; jj < 4; jj++)
                bv[jj] = *(const float4*)(KPs + (tx + 16 * jj) * 68 + d);
#pragma unroll
            for (int i = 0; i < 4; i++)
#pragma unroll
                for (int jj = 0; jj < 4; jj++)
                    s[i][jj] += a[i].x * bv[jj].x + a[i].y * bv[jj].y
                              + a[i].z * bv[jj].z + a[i].w * bv[jj].w;
        }

        // ---- online softmax (row group = 16 lanes) ----
        float p[4][4];
#pragma unroll
        for (int i = 0; i < 4; i++) {
            float mx = -1e30f;
#pragma unroll
            for (int jj = 0; jj < 4; jj++) {
                int col = kt + tx + 16 * jj;
                if (col >= rowkmax[i]) s[i][jj] = -1e30f;
                mx = fmaxf(mx, s[i][jj]);
            }
#pragma unroll
            for (int off = 8; off; off >>= 1)
                mx = fmaxf(mx, __shfl_xor_sync(0xffffffffu, mx, off));
            float mn = fmaxf(m[i], mx);
            float corr = __expf(m[i] - mn);
            float ps = 0.f;
#pragma unroll
            for (int jj = 0; jj < 4; jj++) {
                p[i][jj] = __expf(s[i][jj] - mn);
                ps += p[i][jj];
            }
#pragma unroll
            for (int off = 8; off; off >>= 1)
                ps += __shfl_xor_sync(0xffffffffu, ps, off);
            l[i] = l[i] * corr + ps;
            m[i] = mn;
#pragma unroll
            for (int c = 0; c < 4; c++) o[i][c] *= corr;
        }

        __syncthreads();   // all S reads of K done; KPs becomes P
#pragma unroll
        for (int i = 0; i < 4; i++)
#pragma unroll
            for (int jj = 0; jj < 4; jj++)
                KPs[(ty * 4 + i) * 68 + tx + 16 * jj] = p[i][jj];
        __syncthreads();

        // ---- O += P @ V : O dims tx*4..tx*4+3 ----
#pragma unroll
        for (int k = 0; k < 64; k += 4) {
            float4 pv[4], vv[4];
#pragma unroll
            for (int i = 0; i < 4; i++)
                pv[i] = *(const float4*)(KPs + (ty * 4 + i) * 68 + k);
#pragma unroll
            for (int kk = 0; kk < 4; kk++)
                vv[kk] = *(const float4*)(Vs + (k + kk) * 64 + tx * 4);
#pragma unroll
            for (int i = 0; i < 4; i++) {
                o[i][0] += pv[i].x * vv[0].x + pv[i].y * vv[1].x + pv[i].z * vv[2].x + pv[i].w * vv[3].x;
                o[i][1] += pv[i].x * vv[0].y + pv[i].y * vv[1].y + pv[i].z * vv[2].y + pv[i].w * vv[3].y;
                o[i][2] += pv[i].x * vv[0].z + pv[i].y * vv[1].z + pv[i].z * vv[2].z + pv[i].w * vv[3].z;
                o[i][3] += pv[i].x * vv[0].w + pv[i].y * vv[1].w + pv[i].z * vv[2].w + pv[i].w * vv[3].w;
            }
        }
    }

    // ---- epilogue ----
#pragma unroll
    for (int i = 0; i < 4; i++) {
        int r = q0 + ty * 4 + i;
        if (r < Lq) {
            float inv = 1.f / l[i];
            float4 res;
            res.x = o[i][0] * inv; res.y = o[i][1] * inv;
            res.z = o[i][2] * inv; res.w = o[i][3] * inv;
            size_t ob;
            if (TMP) {
                int nq = (r / 28) * HWP_ + fixed * fs + (r % 28) * vs;
                ob = (size_t)(b * NN_ + nq) * E_ + head * HC_ + tx * 4;
            } else {
                ob = (size_t)(bt * HWP_ + r) * E_ + head * HC_ + tx * 4;
            }
            if (TMP && accum) {
                float4 old = *(const float4*)(out + ob);
                res.x += old.x; res.y += old.y; res.z += old.z; res.w += old.w;
            }
            *(float4*)(out + ob) = res;
        }
    }
}

// ---------------------------------------------------------------------------
extern "C" void kernel_launch(void* const* d_in, const int* in_sizes, int n_in,
                              void* d_out, int out_size)
{
    const float* x      = (const float*)d_in[0];
    const float* w_in   = (const float*)d_in[1];
    const float* b_in   = (const float*)d_in[2];
    const float* w_out  = (const float*)d_in[3];
    const float* b_out  = (const float*)d_in[4];
    const float* w_t    = (const float*)d_in[5];
    const float* b_t    = (const float*)d_in[6];
    const float* w_to   = (const float*)d_in[7];
    const float* b_to   = (const float*)d_in[8];
    const float* alpha  = (const float*)d_in[9];
    float* out = (float*)d_out;

    float *qkv, *sp, *qt, *ot;
    cudaGetSymbolAddress((void**)&qkv, g_qkv);
    cudaGetSymbolAddress((void**)&sp,  g_sp);
    cudaGetSymbolAddress((void**)&qt,  g_qt);
    cudaGetSymbolAddress((void**)&ot,  g_ot);

    cudaFuncSetAttribute(flash_attn<0>, cudaFuncAttributeMaxDynamicSharedMemorySize, FSMEM);
    cudaFuncSetAttribute(flash_attn<1>, cudaFuncAttributeMaxDynamicSharedMemorySize, FSMEM);

    dim3 blk(256);

    // 1) qkv projection: [12544,1536] = x @ w_in^T + b_in
    gemm_kernel<<<dim3(1536 / 128, ROWS_ / 128), blk>>>(
        x, w_in, b_in, qkv, nullptr, ROWS_, 1536, E_, 0, 1.f);

    // 2) spatial attention (13 q-tiles x 8 heads x 16 frames)
    flash_attn<0><<<dim3(13, NH_, B_ * T_), blk, FSMEM>>>(
        qkv, qkv, sp, 0, 0, 0);

    // 3) xs = sp @ w_out^T + b_out  -> d_out
    gemm_kernel<<<dim3(E_ / 128, ROWS_ / 128), blk>>>(
        sp, w_out, b_out, out, nullptr, ROWS_, E_, E_, 0, 1.f);

    // 4) q_t = (x @ w_t^T + b_t) * scale
    gemm_kernel<<<dim3(E_ / 128, ROWS_ / 128), blk>>>(
        x, w_t, b_t, qt, nullptr, ROWS_, E_, E_, 1, SCALE_);

    // 5) temporal-H attention (fixed = w index): ot = o_th
    flash_attn<1><<<dim3(2, NH_, B_ * WW_), blk, FSMEM>>>(
        qkv, qt, ot, /*fs=*/1, /*vs=*/28, /*accum=*/0);

    // 6) temporal-W attention (fixed = h index): ot += o_tw
    flash_attn<1><<<dim3(2, NH_, B_ * HH_), blk, FSMEM>>>(
        qkv, qt, ot, /*fs=*/28, /*vs=*/1, /*accum=*/1);

    // 7) out = xs + alpha * (ot @ w_to^T + b_to)
    gemm_kernel<<<dim3(E_ / 128, ROWS_ / 128), blk>>>(
        ot, w_to, b_to, out, alpha, ROWS_, E_, E_, 2, 1.f);
}

// round 3
// speedup vs baseline: 5.7245x; 2.2824x over previous
#include <cuda_runtime.h>
#include <cuda_bf16.h>
#include <math.h>

#define B_    4
#define T_    4
#define E_    512
#define NH_   8
#define HC_   64
#define HWP_  784
#define NN_   3136
#define ROWS_ 12544
#define SCALE_ 0.125f

__device__ float g_qkv[ROWS_ * 3 * E_];
__device__ float g_sp [ROWS_ * E_];
__device__ float g_qt [ROWS_ * E_];
__device__ float g_ot [ROWS_ * E_];

__device__ __forceinline__ unsigned f2t(float x) {
    unsigned r; asm("cvt.rna.tf32.f32 %0, %1;" : "=r"(r) : "f"(x)); return r;
}
// D += A@B, m16n8k8 tf32, D/C aliased
__device__ __forceinline__ void mma8(float4& d, const unsigned* a, unsigned b0, unsigned b1) {
    asm volatile("mma.sync.aligned.m16n8k8.row.col.f32.tf32.tf32.f32 "
        "{%0,%1,%2,%3},{%4,%5,%6,%7},{%8,%9},{%0,%1,%2,%3};"
        : "+f"(d.x), "+f"(d.y), "+f"(d.z), "+f"(d.w)
        : "r"(a[0]), "r"(a[1]), "r"(a[2]), "r"(a[3]), "r"(b0), "r"(b1));
}

// ---------------------------------------------------------------------------
// tf32 tensor-core GEMM: C[M,N] = A[M,K] @ W[N,K]^T (+bias). Modes:
//   0: C = acc+bias   1: C = (acc+bias)*scl   2: C = C + alpha[n]*(acc+bias)
// BM=BN=128, BK=16, 256 thr = 8 warps (4m x 2n), warp tile 32x64.
// ---------------------------------------------------------------------------
#define GP 132

__global__ __launch_bounds__(256)
void gemm_tf32(const float* __restrict__ A, const float* __restrict__ W,
               const float* __restrict__ bias, float* __restrict__ C,
               const float* __restrict__ alpha,
               int M, int N, int K, int mode, float scl)
{
    __shared__ unsigned As[16 * GP];
    __shared__ unsigned Bs[16 * GP];
    const int bm = blockIdx.y * 128, bn = blockIdx.x * 128;
    const int tid  = threadIdx.x;
    const int warp = tid >> 5, lane = tid & 31;
    const int wm = (warp >> 1) * 32, wn = (warp & 1) * 64;
    const int row = lane >> 2, t4 = lane & 3;

    float4 acc[2][8];
#pragma unroll
    for (int i = 0; i < 2; i++)
#pragma unroll
        for (int j = 0; j < 8; j++) acc[i][j] = make_float4(0.f, 0.f, 0.f, 0.f);

    for (int k0 = 0; k0 < K; k0 += 16) {
#pragma unroll
        for (int it = 0; it < 2; it++) {
            int r  = (tid >> 2) + it * 64;
            int c4 = (tid & 3) * 4;
            float4 a = *(const float4*)(A + (size_t)(bm + r) * K + k0 + c4);
            As[(c4 + 0) * GP + r] = f2t(a.x); As[(c4 + 1) * GP + r] = f2t(a.y);
            As[(c4 + 2) * GP + r] = f2t(a.z); As[(c4 + 3) * GP + r] = f2t(a.w);
            float4 b = *(const float4*)(W + (size_t)(bn + r) * K + k0 + c4);
            Bs[(c4 + 0) * GP + r] = f2t(b.x); Bs[(c4 + 1) * GP + r] = f2t(b.y);
            Bs[(c4 + 2) * GP + r] = f2t(b.z); Bs[(c4 + 3) * GP + r] = f2t(b.w);
        }
        __syncthreads();
#pragma unroll
        for (int ks = 0; ks < 16; ks += 8) {
            unsigned a[2][4];
#pragma unroll
            for (int mt = 0; mt < 2; mt++) {
                int rm = wm + mt * 16 + row;
                a[mt][0] = As[(ks + t4) * GP + rm];
                a[mt][1] = As[(ks + t4) * GP + rm + 8];
                a[mt][2] = As[(ks + t4 + 4) * GP + rm];
                a[mt][3] = As[(ks + t4 + 4) * GP + rm + 8];
            }
#pragma unroll
            for (int nt = 0; nt < 8; nt++) {
                int cn = wn + nt * 8 + row;
                unsigned b0 = Bs[(ks + t4) * GP + cn];
                unsigned b1 = Bs[(ks + t4 + 4) * GP + cn];
                mma8(acc[0][nt], a[0], b0, b1);
                mma8(acc[1][nt], a[1], b0, b1);
            }
        }
        __syncthreads();
    }

#pragma unroll
    for (int mt = 0; mt < 2; mt++) {
        int r0g = bm + wm + mt * 16 + row;
#pragma unroll
        for (int nt = 0; nt < 8; nt++) {
            int cg = bn + wn + nt * 8 + 2 * t4;
            float b0 = bias[cg], b1 = bias[cg + 1];
            float v0 = acc[mt][nt].x + b0, v1 = acc[mt][nt].y + b1;
            float v2 = acc[mt][nt].z + b0, v3 = acc[mt][nt].w + b1;
            if (mode == 1) { v0 *= scl; v1 *= scl; v2 *= scl; v3 *= scl; }
            size_t i0 = (size_t)r0g * N + cg;
            size_t i1 = (size_t)(r0g + 8) * N + cg;
            if (mode == 2) {
                float a0 = alpha[cg], a1 = alpha[cg + 1];
                float2 o0 = *(const float2*)(C + i0);
                float2 o1 = *(const float2*)(C + i1);
                v0 = o0.x + a0 * v0; v1 = o0.y + a1 * v1;
                v2 = o1.x + a0 * v2; v3 = o1.y + a1 * v3;
            }
            *(float2*)(C + i0) = make_float2(v0, v1);
            *(float2*)(C + i1) = make_float2(v2, v3);
        }
    }
}

// ---------------------------------------------------------------------------
// Flash attention with tf32 mma. 128 threads = 4 warps, BQ=64 (16 rows/warp),
// key tiles of 64, D=64. Warp-private P round-trip through reused Q smem.
// TMP=0: spatial (z=bt, L=784, q from qkv*SCALE_, stride 1536)
// TMP=1: temporal axial (z=b*28+fixed, L=112, frame-causal, q from g_qt)
// smem: Qs/Ps[64][68] | Ks[64][68] | Vs[64][68]
// ---------------------------------------------------------------------------
#define FP 68
#define FSMEM (3 * 64 * FP * 4)

template<int TMP>
__global__ __launch_bounds__(128)
void flash_tf32(const float* __restrict__ qkv, const float* __restrict__ qsrc,
                float* __restrict__ out, int fs, int vs, int accum)
{
    extern __shared__ unsigned sm[];
    unsigned* Qs = sm;               // later reused per-warp as P
    unsigned* Ks = sm + 64 * FP;
    unsigned* Vs = sm + 2 * 64 * FP;

    const int tid  = threadIdx.x;
    const int warp = tid >> 5, lane = tid & 31;
    const int row  = lane >> 2, t4 = lane & 3;
    const int head = blockIdx.y;
    const int q0   = blockIdx.x * 64;

    int b = 0, fixed = 0, bt = 0;
    if (TMP) { b = blockIdx.z / 28; fixed = blockIdx.z % 28; }
    else     { bt = blockIdx.z; }

    const int Lq    = TMP ? 112 : HWP_;
    const int lastr = min(q0 + 63, Lq - 1);
    const int kmaxb = TMP ? (lastr / 28 + 1) * 28 : HWP_;

    // ---- stage Q tile ----
    for (int f = tid; f < 1024; f += 128) {
        int r = f >> 4, c4 = (f & 15) << 2;
        int rq = min(q0 + r, Lq - 1);
        float4 v;
        if (TMP) {
            int nq = (rq / 28) * HWP_ + fixed * fs + (rq % 28) * vs;
            v = *(const float4*)(qsrc + (size_t)(b * NN_ + nq) * E_ + head * HC_ + c4);
        } else {
            v = *(const float4*)(qsrc + (size_t)(bt * HWP_ + rq) * 1536 + head * HC_ + c4);
            v.x *= SCALE_; v.y *= SCALE_; v.z *= SCALE_; v.w *= SCALE_;
        }
        uint4 u = make_uint4(f2t(v.x), f2t(v.y), f2t(v.z), f2t(v.w));
        *(uint4*)(Qs + r * FP + c4) = u;
    }
    __syncthreads();

    // ---- Q fragments (held in registers for the whole kernel) ----
    unsigned q[8][4];
    {
        int rm = warp * 16 + row;
#pragma unroll
        for (int kd = 0; kd < 8; kd++) {
            q[kd][0] = Qs[rm * FP + kd * 8 + t4];
            q[kd][1] = Qs[(rm + 8) * FP + kd * 8 + t4];
            q[kd][2] = Qs[rm * FP + kd * 8 + t4 + 4];
            q[kd][3] = Qs[(rm + 8) * FP + kd * 8 + t4 + 4];
        }
    }

    const int r0 = q0 + warp * 16 + row;      // this thread's row pair
    const int lim0 = TMP ? min((r0 / 28 + 1) * 28, 112) : HWP_;
    const int lim1 = TMP ? min(((r0 + 8) / 28 + 1) * 28, 112) : HWP_;
    const int warpLim = TMP ? min(((q0 + warp * 16 + 15) / 28 + 1) * 28, 112) : HWP_;

    float m0 = -1e30f, m1 = -1e30f, l0 = 0.f, l1 = 0.f;
    float4 o[8];
#pragma unroll
    for (int nt = 0; nt < 8; nt++) o[nt] = make_float4(0.f, 0.f, 0.f, 0.f);

    unsigned* Ps = Qs + warp * 16 * FP;       // warp-private P region

    for (int kt = 0; kt < kmaxb; kt += 64) {
        __syncthreads();
        // ---- stage K and V tiles ----
        for (int f = tid; f < 1024; f += 128) {
            int j = f >> 4, c4 = (f & 15) << 2;
            int kk = min(kt + j, kmaxb - 1);
            size_t base;
            if (TMP) {
                int nk = (kk / 28) * HWP_ + fixed * fs + (kk % 28) * vs;
                base = (size_t)(b * NN_ + nk) * 1536 + head * HC_ + c4;
            } else {
                base = (size_t)(bt * HWP_ + kk) * 1536 + head * HC_ + c4;
            }
            float4 kv = *(const float4*)(qkv + base + 512);
            float4 vv = *(const float4*)(qkv + base + 1024);
            *(uint4*)(Ks + j * FP + c4) = make_uint4(f2t(kv.x), f2t(kv.y), f2t(kv.z), f2t(kv.w));
            *(uint4*)(Vs + j * FP + c4) = make_uint4(f2t(vv.x), f2t(vv.y), f2t(vv.z), f2t(vv.w));
        }
        __syncthreads();

        if (kt >= warpLim) continue;          // fully-masked tile for this warp

        // ---- S = Q @ K^T ----
        float4 s[8];
#pragma unroll
        for (int nt = 0; nt < 8; nt++) s[nt] = make_float4(0.f, 0.f, 0.f, 0.f);
#pragma unroll
        for (int kd = 0; kd < 8; kd++) {
#pragma unroll
            for (int nt = 0; nt < 8; nt++) {
                unsigned b0 = Ks[(nt * 8 + row) * FP + kd * 8 + t4];
                unsigned b1 = Ks[(nt * 8 + row) * FP + kd * 8 + t4 + 4];
                mma8(s[nt], q[kd], b0, b1);
            }
        }

        // ---- mask + online softmax ----
        if (TMP || kt + 64 > HWP_) {
            int cb = kt + 2 * t4;
#pragma unroll
            for (int nt = 0; nt < 8; nt++) {
                int c0 = cb + 8 * nt;
                if (c0     >= lim0) s[nt].x = -1e30f;
                if (c0 + 1 >= lim0) s[nt].y = -1e30f;
                if (c0     >= lim1) s[nt].z = -1e30f;
                if (c0 + 1 >= lim1) s[nt].w = -1e30f;
            }
        }
        float mx0 = -1e30f, mx1 = -1e30f;
#pragma unroll
        for (int nt = 0; nt < 8; nt++) {
            mx0 = fmaxf(mx0, fmaxf(s[nt].x, s[nt].y));
            mx1 = fmaxf(mx1, fmaxf(s[nt].z, s[nt].w));
        }
        mx0 = fmaxf(mx0, __shfl_xor_sync(0xffffffffu, mx0, 1));
        mx0 = fmaxf(mx0, __shfl_xor_sync(0xffffffffu, mx0, 2));
        mx1 = fmaxf(mx1, __shfl_xor_sync(0xffffffffu, mx1, 1));
        mx1 = fmaxf(mx1, __shfl_xor_sync(0xffffffffu, mx1, 2));
        float mn0 = fmaxf(m0, mx0), mn1 = fmaxf(m1, mx1);
        float corr0 = __expf(m0 - mn0), corr1 = __expf(m1 - mn1);
        float ps0 = 0.f, ps1 = 0.f;
#pragma unroll
        for (int nt = 0; nt < 8; nt++) {
            s[nt].x = __expf(s[nt].x - mn0); ps0 += s[nt].x;
            s[nt].y = __expf(s[nt].y - mn0); ps0 += s[nt].y;
            s[nt].z = __expf(s[nt].z - mn1); ps1 += s[nt].z;
            s[nt].w = __expf(s[nt].w - mn1); ps1 += s[nt].w;
        }
        ps0 += __shfl_xor_sync(0xffffffffu, ps0, 1);
        ps0 += __shfl_xor_sync(0xffffffffu, ps0, 2);
        ps1 += __shfl_xor_sync(0xffffffffu, ps1, 1);
        ps1 += __shfl_xor_sync(0xffffffffu, ps1, 2);
        l0 = l0 * corr0 + ps0; l1 = l1 * corr1 + ps1;
        m0 = mn0; m1 = mn1;
#pragma unroll
        for (int nt = 0; nt < 8; nt++) {
            o[nt].x *= corr0; o[nt].y *= corr0;
            o[nt].z *= corr1; o[nt].w *= corr1;
        }

        // ---- store P (warp-private, reuses Q smem) ----
#pragma unroll
        for (int nt = 0; nt < 8; nt++) {
            int c = 8 * nt + 2 * t4;
            *(uint2*)(Ps + row * FP + c)       = make_uint2(f2t(s[nt].x), f2t(s[nt].y));
            *(uint2*)(Ps + (row + 8) * FP + c) = make_uint2(f2t(s[nt].z), f2t(s[nt].w));
        }
        __syncwarp();

        // ---- O += P @ V ----
#pragma unroll
        for (int kk = 0; kk < 8; kk++) {
            unsigned a[4];
            a[0] = Ps[row * FP + kk * 8 + t4];
            a[1] = Ps[(row + 8) * FP + kk * 8 + t4];
            a[2] = Ps[row * FP + kk * 8 + t4 + 4];
            a[3] = Ps[(row + 8) * FP + kk * 8 + t4 + 4];
#pragma unroll
            for (int nt = 0; nt < 8; nt++) {
                unsigned b0 = Vs[(kk * 8 + t4) * FP + nt * 8 + row];
                unsigned b1 = Vs[(kk * 8 + t4 + 4) * FP + nt * 8 + row];
                mma8(o[nt], a, b0, b1);
            }
        }
        __syncwarp();   // P reads done before next tile's P stores
    }

    // ---- epilogue ----
    float inv0 = 1.f / l0, inv1 = 1.f / l1;
#pragma unroll
    for (int nt = 0; nt < 8; nt++) {
        int dc = nt * 8 + 2 * t4;
        if (r0 < Lq) {
            size_t ob;
            if (TMP) {
                int nq = (r0 / 28) * HWP_ + fixed * fs + (r0 % 28) * vs;
                ob = (size_t)(b * NN_ + nq) * E_ + head * HC_ + dc;
            } else {
                ob = (size_t)(bt * HWP_ + r0) * E_ + head * HC_ + dc;
            }
            float2 res = make_float2(o[nt].x * inv0, o[nt].y * inv0);
            if (TMP && accum) {
                float2 old = *(const float2*)(out + ob);
                res.x += old.x; res.y += old.y;
            }
            *(float2*)(out + ob) = res;
        }
        if (r0 + 8 < Lq) {
            size_t ob;
            int r1 = r0 + 8;
            if (TMP) {
                int nq = (r1 / 28) * HWP_ + fixed * fs + (r1 % 28) * vs;
                ob = (size_t)(b * NN_ + nq) * E_ + head * HC_ + dc;
            } else {
                ob = (size_t)(bt * HWP_ + r1) * E_ + head * HC_ + dc;
            }
            float2 res = make_float2(o[nt].z * inv1, o[nt].w * inv1);
            if (TMP && accum) {
                float2 old = *(const float2*)(out + ob);
                res.x += old.x; res.y += old.y;
            }
            *(float2*)(out + ob) = res;
        }
    }
}

// ---------------------------------------------------------------------------
extern "C" void kernel_launch(void* const* d_in, const int* in_sizes, int n_in,
                              void* d_out, int out_size)
{
    const float* x      = (const float*)d_in[0];
    const float* w_in   = (const float*)d_in[1];
    const float* b_in   = (const float*)d_in[2];
    const float* w_out  = (const float*)d_in[3];
    const float* b_out  = (const float*)d_in[4];
    const float* w_t    = (const float*)d_in[5];
    const float* b_t    = (const float*)d_in[6];
    const float* w_to   = (const float*)d_in[7];
    const float* b_to   = (const float*)d_in[8];
    const float* alpha  = (const float*)d_in[9];
    float* out = (float*)d_out;

    float *qkv, *sp, *qt, *ot;
    cudaGetSymbolAddress((void**)&qkv, g_qkv);
    cudaGetSymbolAddress((void**)&sp,  g_sp);
    cudaGetSymbolAddress((void**)&qt,  g_qt);
    cudaGetSymbolAddress((void**)&ot,  g_ot);

    cudaFuncSetAttribute(flash_tf32<0>, cudaFuncAttributeMaxDynamicSharedMemorySize, FSMEM);
    cudaFuncSetAttribute(flash_tf32<1>, cudaFuncAttributeMaxDynamicSharedMemorySize, FSMEM);

    // 1) qkv projection
    gemm_tf32<<<dim3(1536 / 128, ROWS_ / 128), 256>>>(
        x, w_in, b_in, qkv, nullptr, ROWS_, 1536, E_, 0, 1.f);

    // 2) spatial attention
    flash_tf32<0><<<dim3(13, NH_, B_ * T_), 128, FSMEM>>>(qkv, qkv, sp, 0, 0, 0);

    // 3) xs = sp @ w_out^T + b_out -> d_out
    gemm_tf32<<<dim3(E_ / 128, ROWS_ / 128), 256>>>(
        sp, w_out, b_out, out, nullptr, ROWS_, E_, E_, 0, 1.f);

    // 4) q_t = (x @ w_t^T + b_t) * scale
    gemm_tf32<<<dim3(E_ / 128, ROWS_ / 128), 256>>>(
        x, w_t, b_t, qt, nullptr, ROWS_, E_, E_, 1, SCALE_);

    // 5) temporal-H: ot = o_th
    flash_tf32<1><<<dim3(2, NH_, B_ * 28), 128, FSMEM>>>(qkv, qt, ot, 1, 28, 0);

    // 6) temporal-W: ot += o_tw
    flash_tf32<1><<<dim3(2, NH_, B_ * 28), 128, FSMEM>>>(qkv, qt, ot, 28, 1, 1);

    // 7) out = xs + alpha * (ot @ w_to^T + b_to)
    gemm_tf32<<<dim3(E_ / 128, ROWS_ / 128), 256>>>(
        ot, w_to, b_to, out, alpha, ROWS_, E_, E_, 2, 1.f);
}